// round 13
// baseline (speedup 1.0000x reference)
#include <cuda_runtime.h>
#include <cstdint>

#define NN 100000
#define NE 1600000
#define NEG_SLOPE 0.2f
#define BN_EPS 1e-5f

// ---------------- scratch (static __device__, no allocation) ----------------
__device__ __align__(16) float g_h[(size_t)NN * 128];   // GEMM output [N,4,32]
__device__ __align__(16) float g_y[(size_t)NN * 32];    // per-layer node features
__device__ __align__(16) float g_alS[(size_t)NN * 4];
__device__ __align__(16) float g_alD[(size_t)NN * 4];
__device__ int g_deg[NN];
__device__ int g_rowptr[NN + 1];
__device__ int g_cursor[NN];
__device__ int g_csr_src[NE];
__device__ float g_bn[2 * 32 * 32];                     // strided sums / sumsq
__device__ float g_scale[32];
__device__ float g_shift[32];

__device__ __forceinline__ float leaky(float e) {
    return e >= 0.f ? e : NEG_SLOPE * e;
}

// ---------------- CSR build ----------------
__global__ void hist_k(const int* __restrict__ dst, int* __restrict__ deg) {
    int i = blockIdx.x * blockDim.x + threadIdx.x;
    if (i < NE) atomicAdd(&deg[dst[i]], 1);
}

// single block, 1024 threads: chunked exclusive scan of deg -> rowptr, cursor
__global__ void scan_k(const int* __restrict__ deg, int* __restrict__ rowptr,
                       int* __restrict__ cursor) {
    __shared__ int sc[1024];
    const int tid = threadIdx.x;
    const int CH = (NN + 1023) / 1024;  // 98
    const int base = tid * CH;
    int s = 0;
    for (int i = 0; i < CH; ++i) {
        int idx = base + i;
        if (idx < NN) s += deg[idx];
    }
    sc[tid] = s;
    __syncthreads();
    for (int off = 1; off < 1024; off <<= 1) {
        int v = (tid >= off) ? sc[tid - off] : 0;
        __syncthreads();
        sc[tid] += v;
        __syncthreads();
    }
    int run = sc[tid] - s;
    for (int i = 0; i < CH; ++i) {
        int idx = base + i;
        if (idx < NN) {
            rowptr[idx] = run;
            cursor[idx] = run;
            run += deg[idx];
        }
    }
    if (tid == 1023) rowptr[NN] = sc[1023];
}

__global__ void scatter_build_k(const int* __restrict__ src, const int* __restrict__ dst,
                                int* __restrict__ cursor, int* __restrict__ csr_src) {
    int i = blockIdx.x * blockDim.x + threadIdx.x;
    if (i >= NE) return;
    int p = atomicAdd(&cursor[dst[i]], 1);
    csr_src[p] = src[i];
}

// ---------------- GEMM + attention logits (fused prev-layer BN+ReLU) ----------------
// Register-blocked: 128x128 tile, 256 threads (16x16), 8x8 micro-tile per thread.
template<int F>
__global__ void gemm_al(const float* __restrict__ x,     // [N,F]
                        const float* __restrict__ W,     // [F,128] (k-major)
                        const float* __restrict__ aS,    // [128]
                        const float* __restrict__ aD,    // [128]
                        const float* __restrict__ scale, // [F] or null
                        const float* __restrict__ shift, // [F] or null
                        float* __restrict__ h,           // [N,128]
                        float* __restrict__ alS,         // [N,4]
                        float* __restrict__ alD,         // [N,4]
                        int useBN)
{
    __shared__ float As[32][132];   // [k][m]
    __shared__ float Bs[32][132];   // [k][n]
    const int tid = threadIdx.x;
    const int tx = tid & 15;
    const int ty = tid >> 4;
    const int n0 = blockIdx.x * 128;
    const int col0 = tx * 8;

    const int ar = tid >> 1;          // A-load row 0..127
    const int ah = (tid & 1) * 16;    // A-load k-half offset
    const int bk = tid >> 3;          // B-load k 0..31
    const int bs = (tid & 7) * 16;    // B-load col segment

    float acc[8][8];
#pragma unroll
    for (int i = 0; i < 8; ++i)
#pragma unroll
        for (int j = 0; j < 8; ++j) acc[i][j] = 0.f;

    for (int k0 = 0; k0 < F; k0 += 32) {
        // ---- A load (transpose into As[k][m]), fused BN+ReLU ----
        {
            int n = n0 + ar;
            const float* xp = x + (size_t)n * F + k0 + ah;
#pragma unroll
            for (int q = 0; q < 4; ++q) {
                float4 v = make_float4(0.f, 0.f, 0.f, 0.f);
                if (n < NN) {
                    v = *(const float4*)(xp + q * 4);
                    if (useBN) {
                        int k = k0 + ah + q * 4;
                        v.x = fmaxf(fmaf(v.x, scale[k],     shift[k]),     0.f);
                        v.y = fmaxf(fmaf(v.y, scale[k + 1], shift[k + 1]), 0.f);
                        v.z = fmaxf(fmaf(v.z, scale[k + 2], shift[k + 2]), 0.f);
                        v.w = fmaxf(fmaf(v.w, scale[k + 3], shift[k + 3]), 0.f);
                    }
                }
                As[ah + q * 4 + 0][ar] = v.x;
                As[ah + q * 4 + 1][ar] = v.y;
                As[ah + q * 4 + 2][ar] = v.z;
                As[ah + q * 4 + 3][ar] = v.w;
            }
        }
        // ---- B load (direct copy into Bs[k][n]) ----
        {
            const float* wp = W + (size_t)(k0 + bk) * 128 + bs;
#pragma unroll
            for (int q = 0; q < 4; ++q)
                *(float4*)&Bs[bk][bs + q * 4] = *(const float4*)(wp + q * 4);
        }
        __syncthreads();

#pragma unroll 4
        for (int k = 0; k < 32; ++k) {
            float4 a0 = *(const float4*)&As[k][ty * 8];
            float4 a1 = *(const float4*)&As[k][ty * 8 + 4];
            float4 b0 = *(const float4*)&Bs[k][col0];
            float4 b1 = *(const float4*)&Bs[k][col0 + 4];
            float a[8] = {a0.x, a0.y, a0.z, a0.w, a1.x, a1.y, a1.z, a1.w};
            float b[8] = {b0.x, b0.y, b0.z, b0.w, b1.x, b1.y, b1.z, b1.w};
#pragma unroll
            for (int i = 0; i < 8; ++i)
#pragma unroll
                for (int j = 0; j < 8; ++j)
                    acc[i][j] = fmaf(a[i], b[j], acc[i][j]);
        }
        __syncthreads();
    }

    // ---- epilogue: h stores + fused attention logits ----
    float4 s0 = *(const float4*)(aS + col0);
    float4 s1 = *(const float4*)(aS + col0 + 4);
    float4 d0 = *(const float4*)(aD + col0);
    float4 d1 = *(const float4*)(aD + col0 + 4);
    float aSv[8] = {s0.x, s0.y, s0.z, s0.w, s1.x, s1.y, s1.z, s1.w};
    float aDv[8] = {d0.x, d0.y, d0.z, d0.w, d1.x, d1.y, d1.z, d1.w};

#pragma unroll
    for (int i = 0; i < 8; ++i) {
        int n = n0 + ty * 8 + i;
        bool ok = (n < NN);
        if (ok) {
            *(float4*)&h[(size_t)n * 128 + col0] =
                make_float4(acc[i][0], acc[i][1], acc[i][2], acc[i][3]);
            *(float4*)&h[(size_t)n * 128 + col0 + 4] =
                make_float4(acc[i][4], acc[i][5], acc[i][6], acc[i][7]);
        }
        float vs = 0.f, vd = 0.f;
#pragma unroll
        for (int j = 0; j < 8; ++j) {
            vs = fmaf(acc[i][j], aSv[j], vs);
            vd = fmaf(acc[i][j], aDv[j], vd);
        }
        vs += __shfl_xor_sync(0xffffffffu, vs, 1);
        vd += __shfl_xor_sync(0xffffffffu, vd, 1);
        vs += __shfl_xor_sync(0xffffffffu, vs, 2);
        vd += __shfl_xor_sync(0xffffffffu, vd, 2);
        if ((tx & 3) == 0 && ok) {
            alS[n * 4 + (tx >> 2)] = vs;
            alD[n * 4 + (tx >> 2)] = vd;
        }
    }
}

// ---------------- fused attention + aggregate + head-mean + bias ----------------
// Single-pass, unnormalized accumulate; stream loop unrolled x4 so 4 independent
// h-row loads are in flight (MLP=4) instead of one serial L2 round-trip per edge.
__global__ void gather_k(const int* __restrict__ rowptr,
                         const int* __restrict__ csr_src,
                         const float4* __restrict__ alS4,  // [N] (4 heads)
                         const float4* __restrict__ alD4,  // [N]
                         const float4* __restrict__ h,     // [N,32] float4
                         const float4* __restrict__ bias4, // [8]
                         float4* __restrict__ out4)        // [N,8] float4
{
    __shared__ float4 s_ee[8][32];
    __shared__ int    s_sid[8][32];
    int gid = blockIdx.x * blockDim.x + threadIdx.x;
    int n = gid >> 5;
    if (n >= NN) return;
    const int warp = threadIdx.x >> 5;
    const int lane = gid & 31;
    const int head = lane >> 3;

    const int beg = rowptr[n];
    const int end = rowptr[n + 1];
    const float4 ad4 = alD4[n];   // broadcast load

    float4 den4 = make_float4(0.f, 0.f, 0.f, 0.f);
    float4 acc  = make_float4(0.f, 0.f, 0.f, 0.f);

    for (int base = beg; base < end; base += 32) {
        const int cnt = min(32, end - base);
        if (lane < cnt) {
            int s = csr_src[base + lane];
            float4 a = alS4[s];
            float4 ee;
            ee.x = __expf(leaky(a.x + ad4.x));
            ee.y = __expf(leaky(a.y + ad4.y));
            ee.z = __expf(leaky(a.z + ad4.z));
            ee.w = __expf(leaky(a.w + ad4.w));
            den4.x += ee.x; den4.y += ee.y; den4.z += ee.z; den4.w += ee.w;
            s_sid[warp][lane] = s;
            s_ee[warp][lane] = ee;
        }
        __syncwarp();
        int j = 0;
        for (; j + 4 <= cnt; j += 4) {
            int s0 = s_sid[warp][j];
            int s1 = s_sid[warp][j + 1];
            int s2 = s_sid[warp][j + 2];
            int s3 = s_sid[warp][j + 3];
            float w0 = reinterpret_cast<const float*>(&s_ee[warp][j])[head];
            float w1 = reinterpret_cast<const float*>(&s_ee[warp][j + 1])[head];
            float w2 = reinterpret_cast<const float*>(&s_ee[warp][j + 2])[head];
            float w3 = reinterpret_cast<const float*>(&s_ee[warp][j + 3])[head];
            float4 h0 = h[(size_t)s0 * 32 + lane];   // 4 independent LDGs
            float4 h1 = h[(size_t)s1 * 32 + lane];
            float4 h2 = h[(size_t)s2 * 32 + lane];
            float4 h3 = h[(size_t)s3 * 32 + lane];
            acc.x = fmaf(w0, h0.x, acc.x); acc.y = fmaf(w0, h0.y, acc.y);
            acc.z = fmaf(w0, h0.z, acc.z); acc.w = fmaf(w0, h0.w, acc.w);
            acc.x = fmaf(w1, h1.x, acc.x); acc.y = fmaf(w1, h1.y, acc.y);
            acc.z = fmaf(w1, h1.z, acc.z); acc.w = fmaf(w1, h1.w, acc.w);
            acc.x = fmaf(w2, h2.x, acc.x); acc.y = fmaf(w2, h2.y, acc.y);
            acc.z = fmaf(w2, h2.z, acc.z); acc.w = fmaf(w2, h2.w, acc.w);
            acc.x = fmaf(w3, h3.x, acc.x); acc.y = fmaf(w3, h3.y, acc.y);
            acc.z = fmaf(w3, h3.z, acc.z); acc.w = fmaf(w3, h3.w, acc.w);
        }
        for (; j < cnt; ++j) {
            int s = s_sid[warp][j];
            float w = reinterpret_cast<const float*>(&s_ee[warp][j])[head];
            float4 hv = h[(size_t)s * 32 + lane];
            acc.x = fmaf(w, hv.x, acc.x);
            acc.y = fmaf(w, hv.y, acc.y);
            acc.z = fmaf(w, hv.z, acc.z);
            acc.w = fmaf(w, hv.w, acc.w);
        }
        __syncwarp();
    }

    // reduce den across lanes (all 4 heads)
#pragma unroll
    for (int off = 16; off > 0; off >>= 1) {
        den4.x += __shfl_xor_sync(0xffffffffu, den4.x, off);
        den4.y += __shfl_xor_sync(0xffffffffu, den4.y, off);
        den4.z += __shfl_xor_sync(0xffffffffu, den4.z, off);
        den4.w += __shfl_xor_sync(0xffffffffu, den4.w, off);
    }
    const float den = (head == 0) ? den4.x : (head == 1) ? den4.y
                    : (head == 2) ? den4.z : den4.w;
    const float wsc = (den > 0.f) ? 0.25f / den : 0.f;
    acc.x *= wsc; acc.y *= wsc; acc.z *= wsc; acc.w *= wsc;

    // head mean: sum the 4 heads (lanes differing in bits 3,4)
#pragma unroll
    for (int off = 8; off <= 16; off <<= 1) {
        acc.x += __shfl_xor_sync(0xffffffffu, acc.x, off);
        acc.y += __shfl_xor_sync(0xffffffffu, acc.y, off);
        acc.z += __shfl_xor_sync(0xffffffffu, acc.z, off);
        acc.w += __shfl_xor_sync(0xffffffffu, acc.w, off);
    }

    if (lane < 8) {
        float4 b = bias4[lane];
        float4 r;
        r.x = acc.x + b.x; r.y = acc.y + b.y;
        r.z = acc.z + b.z; r.w = acc.w + b.w;
        out4[(size_t)n * 8 + lane] = r;
    }
}

// ---------------- BN stats over y ----------------
__global__ void bn_stats_k(const float* __restrict__ y,
                           float* __restrict__ bnsum, float* __restrict__ bnsq)
{
    __shared__ float s1[1024];
    __shared__ float s2[1024];
    int tid = threadIdx.x;
    int c = tid & 31;
    int n = blockIdx.x * 32 + (tid >> 5);
    float val = (n < NN) ? y[(size_t)n * 32 + c] : 0.f;
    s1[tid] = val;
    s2[tid] = val * val;
    __syncthreads();
    for (int st = 512; st >= 32; st >>= 1) {
        if (tid < st) { s1[tid] += s1[tid + st]; s2[tid] += s2[tid + st]; }
        __syncthreads();
    }
    if (tid < 32) {
        atomicAdd(&bnsum[tid * 32], s1[tid]);
        atomicAdd(&bnsq[tid * 32], s2[tid]);
    }
}

__global__ void bn_params_k(const float* __restrict__ bnsum, const float* __restrict__ bnsq,
                            const float* __restrict__ g, const float* __restrict__ be,
                            float* __restrict__ scale, float* __restrict__ shift)
{
    int c = threadIdx.x;
    if (c >= 32) return;
    float mu = bnsum[c * 32] * (1.f / NN);
    float var = bnsq[c * 32] * (1.f / NN) - mu * mu;
    float sc = g[c] * rsqrtf(var + BN_EPS);
    scale[c] = sc;
    shift[c] = be[c] - mu * sc;
}

// ---------------- host ----------------
extern "C" void kernel_launch(void* const* d_in, const int* in_sizes, int n_in,
                              void* d_out, int out_size)
{
    const float* x   = (const float*)d_in[0];
    const int*   ei  = (const int*)  d_in[1];
    const float* ea  = (const float*)d_in[2];
    const float* W[3]   = {(const float*)d_in[3],  (const float*)d_in[9],  (const float*)d_in[15]};
    const float* aS[3]  = {(const float*)d_in[4],  (const float*)d_in[10], (const float*)d_in[16]};
    const float* aD[3]  = {(const float*)d_in[5],  (const float*)d_in[11], (const float*)d_in[17]};
    const float* bia[3] = {(const float*)d_in[6],  (const float*)d_in[12], (const float*)d_in[18]};
    const float* gam[2] = {(const float*)d_in[7],  (const float*)d_in[13]};
    const float* bet[2] = {(const float*)d_in[8],  (const float*)d_in[14]};
    const int* src = ei;
    const int* dst = ei + NE;

    void *ph, *py, *pals, *pald, *pdeg, *prow, *pcur, *pcsr, *pbn, *psc, *psh;
    cudaGetSymbolAddress(&ph, g_h);
    cudaGetSymbolAddress(&py, g_y);
    cudaGetSymbolAddress(&pals, g_alS);
    cudaGetSymbolAddress(&pald, g_alD);
    cudaGetSymbolAddress(&pdeg, g_deg);
    cudaGetSymbolAddress(&prow, g_rowptr);
    cudaGetSymbolAddress(&pcur, g_cursor);
    cudaGetSymbolAddress(&pcsr, g_csr_src);
    cudaGetSymbolAddress(&pbn, g_bn);
    cudaGetSymbolAddress(&psc, g_scale);
    cudaGetSymbolAddress(&psh, g_shift);

    const int GEMM_BLOCKS = (NN + 127) / 128;     // 782
    const int EB = (NE + 255) / 256;              // 6250
    const int GB = (NN * 32 + 255) / 256;         // 12500
    const int BB = (NN + 31) / 32;                // 3125

    // ---- CSR build (once; reused by all 3 layers) ----
    cudaMemsetAsync(pdeg, 0, NN * sizeof(int));
    hist_k<<<EB, 256>>>(dst, (int*)pdeg);
    scan_k<<<1, 1024>>>((const int*)pdeg, (int*)prow, (int*)pcur);
    scatter_build_k<<<EB, 256>>>(src, dst, (int*)pcur, (int*)pcsr);

    for (int L = 0; L < 3; ++L) {
        if (L == 0) {
            gemm_al<128><<<GEMM_BLOCKS, 256>>>(
                x, W[0], aS[0], aD[0], nullptr, nullptr,
                (float*)ph, (float*)pals, (float*)pald, 0);
        } else {
            gemm_al<32><<<GEMM_BLOCKS, 256>>>(
                (const float*)py, W[L], aS[L], aD[L],
                (const float*)psc, (const float*)psh,
                (float*)ph, (float*)pals, (float*)pald, 1);
        }

        float* dest = (L < 2) ? (float*)py : (float*)d_out;
        gather_k<<<GB, 256>>>((const int*)prow, (const int*)pcsr,
                              (const float4*)pals, (const float4*)pald,
                              (const float4*)ph, (const float4*)bia[L],
                              (float4*)dest);

        if (L < 2) {
            cudaMemsetAsync(pbn, 0, 2 * 32 * 32 * sizeof(float));
            bn_stats_k<<<BB, 1024>>>((const float*)py, (float*)pbn, (float*)pbn + 1024);
            bn_params_k<<<1, 32>>>((const float*)pbn, (const float*)pbn + 1024,
                                   gam[L], bet[L], (float*)psc, (float*)psh);
        }
    }

    cudaMemcpyAsync((float*)d_out + (size_t)NN * 32, ea,
                    (size_t)NE * 8 * sizeof(float), cudaMemcpyDeviceToDevice);
}

// round 15
// speedup vs baseline: 1.1034x; 1.1034x over previous
#include <cuda_runtime.h>
#include <cuda_fp16.h>
#include <cstdint>

#define NN 100000
#define NE 1600000
#define NEG_SLOPE 0.2f
#define BN_EPS 1e-5f

// ---------------- scratch (static __device__, no allocation) ----------------
__device__ __align__(16) __half g_h[(size_t)NN * 128];  // GEMM output [N,4,32] fp16
__device__ __align__(16) float g_y[(size_t)NN * 32];    // per-layer node features
__device__ __align__(16) float g_alS[(size_t)NN * 4];
__device__ __align__(16) float g_alD[(size_t)NN * 4];
__device__ int g_deg[NN];
__device__ int g_rowptr[NN + 1];
__device__ int g_cursor[NN];
__device__ int g_csr_src[NE];
__device__ float g_bn[2 * 32 * 32];                     // strided sums / sumsq
__device__ float g_scale[32];
__device__ float g_shift[32];

__device__ __forceinline__ float leaky(float e) {
    return e >= 0.f ? e : NEG_SLOPE * e;
}

// ---------------- CSR build ----------------
__global__ void hist_k(const int* __restrict__ dst, int* __restrict__ deg) {
    int i = blockIdx.x * blockDim.x + threadIdx.x;
    if (i < NE) atomicAdd(&deg[dst[i]], 1);
}

// single block, 1024 threads: chunked exclusive scan of deg -> rowptr, cursor
__global__ void scan_k(const int* __restrict__ deg, int* __restrict__ rowptr,
                       int* __restrict__ cursor) {
    __shared__ int sc[1024];
    const int tid = threadIdx.x;
    const int CH = (NN + 1023) / 1024;  // 98
    const int base = tid * CH;
    int s = 0;
    for (int i = 0; i < CH; ++i) {
        int idx = base + i;
        if (idx < NN) s += deg[idx];
    }
    sc[tid] = s;
    __syncthreads();
    for (int off = 1; off < 1024; off <<= 1) {
        int v = (tid >= off) ? sc[tid - off] : 0;
        __syncthreads();
        sc[tid] += v;
        __syncthreads();
    }
    int run = sc[tid] - s;
    for (int i = 0; i < CH; ++i) {
        int idx = base + i;
        if (idx < NN) {
            rowptr[idx] = run;
            cursor[idx] = run;
            run += deg[idx];
        }
    }
    if (tid == 1023) rowptr[NN] = sc[1023];
}

__global__ void scatter_build_k(const int* __restrict__ src, const int* __restrict__ dst,
                                int* __restrict__ cursor, int* __restrict__ csr_src) {
    int i = blockIdx.x * blockDim.x + threadIdx.x;
    if (i >= NE) return;
    int p = atomicAdd(&cursor[dst[i]], 1);
    csr_src[p] = src[i];
}

// ---------------- GEMM + attention logits (fused prev-layer BN+ReLU) ----------------
// Register-blocked: 128x128 tile, 256 threads (16x16), 8x8 micro-tile per thread.
// h written as fp16 (halves gather traffic); logits computed from fp32 accs.
template<int F>
__global__ void gemm_al(const float* __restrict__ x,     // [N,F]
                        const float* __restrict__ W,     // [F,128] (k-major)
                        const float* __restrict__ aS,    // [128]
                        const float* __restrict__ aD,    // [128]
                        const float* __restrict__ scale, // [F] or null
                        const float* __restrict__ shift, // [F] or null
                        __half* __restrict__ h,          // [N,128] fp16
                        float* __restrict__ alS,         // [N,4]
                        float* __restrict__ alD,         // [N,4]
                        int useBN)
{
    __shared__ float As[32][132];   // [k][m]
    __shared__ float Bs[32][132];   // [k][n]
    const int tid = threadIdx.x;
    const int tx = tid & 15;
    const int ty = tid >> 4;
    const int n0 = blockIdx.x * 128;
    const int col0 = tx * 8;

    const int ar = tid >> 1;          // A-load row 0..127
    const int ah = (tid & 1) * 16;    // A-load k-half offset
    const int bk = tid >> 3;          // B-load k 0..31
    const int bs = (tid & 7) * 16;    // B-load col segment

    float acc[8][8];
#pragma unroll
    for (int i = 0; i < 8; ++i)
#pragma unroll
        for (int j = 0; j < 8; ++j) acc[i][j] = 0.f;

    for (int k0 = 0; k0 < F; k0 += 32) {
        // ---- A load (transpose into As[k][m]), fused BN+ReLU ----
        {
            int n = n0 + ar;
            const float* xp = x + (size_t)n * F + k0 + ah;
#pragma unroll
            for (int q = 0; q < 4; ++q) {
                float4 v = make_float4(0.f, 0.f, 0.f, 0.f);
                if (n < NN) {
                    v = *(const float4*)(xp + q * 4);
                    if (useBN) {
                        int k = k0 + ah + q * 4;
                        v.x = fmaxf(fmaf(v.x, scale[k],     shift[k]),     0.f);
                        v.y = fmaxf(fmaf(v.y, scale[k + 1], shift[k + 1]), 0.f);
                        v.z = fmaxf(fmaf(v.z, scale[k + 2], shift[k + 2]), 0.f);
                        v.w = fmaxf(fmaf(v.w, scale[k + 3], shift[k + 3]), 0.f);
                    }
                }
                As[ah + q * 4 + 0][ar] = v.x;
                As[ah + q * 4 + 1][ar] = v.y;
                As[ah + q * 4 + 2][ar] = v.z;
                As[ah + q * 4 + 3][ar] = v.w;
            }
        }
        // ---- B load (direct copy into Bs[k][n]) ----
        {
            const float* wp = W + (size_t)(k0 + bk) * 128 + bs;
#pragma unroll
            for (int q = 0; q < 4; ++q)
                *(float4*)&Bs[bk][bs + q * 4] = *(const float4*)(wp + q * 4);
        }
        __syncthreads();

#pragma unroll 4
        for (int k = 0; k < 32; ++k) {
            float4 a0 = *(const float4*)&As[k][ty * 8];
            float4 a1 = *(const float4*)&As[k][ty * 8 + 4];
            float4 b0 = *(const float4*)&Bs[k][col0];
            float4 b1 = *(const float4*)&Bs[k][col0 + 4];
            float a[8] = {a0.x, a0.y, a0.z, a0.w, a1.x, a1.y, a1.z, a1.w};
            float b[8] = {b0.x, b0.y, b0.z, b0.w, b1.x, b1.y, b1.z, b1.w};
#pragma unroll
            for (int i = 0; i < 8; ++i)
#pragma unroll
                for (int j = 0; j < 8; ++j)
                    acc[i][j] = fmaf(a[i], b[j], acc[i][j]);
        }
        __syncthreads();
    }

    // ---- epilogue: fp16 h stores + fused attention logits ----
    float4 s0 = *(const float4*)(aS + col0);
    float4 s1 = *(const float4*)(aS + col0 + 4);
    float4 d0 = *(const float4*)(aD + col0);
    float4 d1 = *(const float4*)(aD + col0 + 4);
    float aSv[8] = {s0.x, s0.y, s0.z, s0.w, s1.x, s1.y, s1.z, s1.w};
    float aDv[8] = {d0.x, d0.y, d0.z, d0.w, d1.x, d1.y, d1.z, d1.w};

#pragma unroll
    for (int i = 0; i < 8; ++i) {
        int n = n0 + ty * 8 + i;
        bool ok = (n < NN);
        if (ok) {
            __half hv[8];
#pragma unroll
            for (int j = 0; j < 8; ++j) hv[j] = __float2half(acc[i][j]);
            *(uint4*)&h[(size_t)n * 128 + col0] = *(const uint4*)hv;
        }
        float vs = 0.f, vd = 0.f;
#pragma unroll
        for (int j = 0; j < 8; ++j) {
            vs = fmaf(acc[i][j], aSv[j], vs);
            vd = fmaf(acc[i][j], aDv[j], vd);
        }
        vs += __shfl_xor_sync(0xffffffffu, vs, 1);
        vd += __shfl_xor_sync(0xffffffffu, vd, 1);
        vs += __shfl_xor_sync(0xffffffffu, vs, 2);
        vd += __shfl_xor_sync(0xffffffffu, vd, 2);
        if ((tx & 3) == 0 && ok) {
            alS[n * 4 + (tx >> 2)] = vs;
            alD[n * 4 + (tx >> 2)] = vd;
        }
    }
}

// ---------------- fused attention + aggregate + head-mean + bias ----------------
// Single-pass, unnormalized accumulate. h is fp16: lane loads 8B (4 halfs),
// warp-load per edge = 256B = 2 L1tex wavefronts (was 4 with fp32).
__global__ void gather_k(const int* __restrict__ rowptr,
                         const int* __restrict__ csr_src,
                         const float4* __restrict__ alS4,  // [N] (4 heads)
                         const float4* __restrict__ alD4,  // [N]
                         const __half* __restrict__ h,     // [N,128] fp16
                         const float4* __restrict__ bias4, // [8]
                         float4* __restrict__ out4)        // [N,8] float4
{
    __shared__ float4 s_ee[8][32];
    __shared__ int    s_sid[8][32];
    int gid = blockIdx.x * blockDim.x + threadIdx.x;
    int n = gid >> 5;
    if (n >= NN) return;
    const int warp = threadIdx.x >> 5;
    const int lane = gid & 31;
    const int head = lane >> 3;

    const int beg = rowptr[n];
    const int end = rowptr[n + 1];
    const float4 ad4 = alD4[n];   // broadcast load

    float4 den4 = make_float4(0.f, 0.f, 0.f, 0.f);
    float4 acc  = make_float4(0.f, 0.f, 0.f, 0.f);

    for (int base = beg; base < end; base += 32) {
        const int cnt = min(32, end - base);
        if (lane < cnt) {
            int s = csr_src[base + lane];
            float4 a = alS4[s];
            float4 ee;
            ee.x = __expf(leaky(a.x + ad4.x));
            ee.y = __expf(leaky(a.y + ad4.y));
            ee.z = __expf(leaky(a.z + ad4.z));
            ee.w = __expf(leaky(a.w + ad4.w));
            den4.x += ee.x; den4.y += ee.y; den4.z += ee.z; den4.w += ee.w;
            s_sid[warp][lane] = s;
            s_ee[warp][lane] = ee;
        }
        __syncwarp();
        int j = 0;
        for (; j + 4 <= cnt; j += 4) {
            int s0 = s_sid[warp][j];
            int s1 = s_sid[warp][j + 1];
            int s2 = s_sid[warp][j + 2];
            int s3 = s_sid[warp][j + 3];
            float w0 = reinterpret_cast<const float*>(&s_ee[warp][j])[head];
            float w1 = reinterpret_cast<const float*>(&s_ee[warp][j + 1])[head];
            float w2 = reinterpret_cast<const float*>(&s_ee[warp][j + 2])[head];
            float w3 = reinterpret_cast<const float*>(&s_ee[warp][j + 3])[head];
            uint2 r0 = *(const uint2*)(h + (size_t)s0 * 128 + lane * 4);
            uint2 r1 = *(const uint2*)(h + (size_t)s1 * 128 + lane * 4);
            uint2 r2 = *(const uint2*)(h + (size_t)s2 * 128 + lane * 4);
            uint2 r3 = *(const uint2*)(h + (size_t)s3 * 128 + lane * 4);
            float2 f0a = __half22float2(*reinterpret_cast<__half2*>(&r0.x));
            float2 f0b = __half22float2(*reinterpret_cast<__half2*>(&r0.y));
            float2 f1a = __half22float2(*reinterpret_cast<__half2*>(&r1.x));
            float2 f1b = __half22float2(*reinterpret_cast<__half2*>(&r1.y));
            float2 f2a = __half22float2(*reinterpret_cast<__half2*>(&r2.x));
            float2 f2b = __half22float2(*reinterpret_cast<__half2*>(&r2.y));
            float2 f3a = __half22float2(*reinterpret_cast<__half2*>(&r3.x));
            float2 f3b = __half22float2(*reinterpret_cast<__half2*>(&r3.y));
            acc.x = fmaf(w0, f0a.x, acc.x); acc.y = fmaf(w0, f0a.y, acc.y);
            acc.z = fmaf(w0, f0b.x, acc.z); acc.w = fmaf(w0, f0b.y, acc.w);
            acc.x = fmaf(w1, f1a.x, acc.x); acc.y = fmaf(w1, f1a.y, acc.y);
            acc.z = fmaf(w1, f1b.x, acc.z); acc.w = fmaf(w1, f1b.y, acc.w);
            acc.x = fmaf(w2, f2a.x, acc.x); acc.y = fmaf(w2, f2a.y, acc.y);
            acc.z = fmaf(w2, f2b.x, acc.z); acc.w = fmaf(w2, f2b.y, acc.w);
            acc.x = fmaf(w3, f3a.x, acc.x); acc.y = fmaf(w3, f3a.y, acc.y);
            acc.z = fmaf(w3, f3b.x, acc.z); acc.w = fmaf(w3, f3b.y, acc.w);
        }
        for (; j < cnt; ++j) {
            int s = s_sid[warp][j];
            float w = reinterpret_cast<const float*>(&s_ee[warp][j])[head];
            uint2 r = *(const uint2*)(h + (size_t)s * 128 + lane * 4);
            float2 fa = __half22float2(*reinterpret_cast<__half2*>(&r.x));
            float2 fb = __half22float2(*reinterpret_cast<__half2*>(&r.y));
            acc.x = fmaf(w, fa.x, acc.x);
            acc.y = fmaf(w, fa.y, acc.y);
            acc.z = fmaf(w, fb.x, acc.z);
            acc.w = fmaf(w, fb.y, acc.w);
        }
        __syncwarp();
    }

    // reduce den across lanes (all 4 heads)
#pragma unroll
    for (int off = 16; off > 0; off >>= 1) {
        den4.x += __shfl_xor_sync(0xffffffffu, den4.x, off);
        den4.y += __shfl_xor_sync(0xffffffffu, den4.y, off);
        den4.z += __shfl_xor_sync(0xffffffffu, den4.z, off);
        den4.w += __shfl_xor_sync(0xffffffffu, den4.w, off);
    }
    const float den = (head == 0) ? den4.x : (head == 1) ? den4.y
                    : (head == 2) ? den4.z : den4.w;
    const float wsc = (den > 0.f) ? 0.25f / den : 0.f;
    acc.x *= wsc; acc.y *= wsc; acc.z *= wsc; acc.w *= wsc;

    // head mean: sum the 4 heads (lanes differing in bits 3,4)
#pragma unroll
    for (int off = 8; off <= 16; off <<= 1) {
        acc.x += __shfl_xor_sync(0xffffffffu, acc.x, off);
        acc.y += __shfl_xor_sync(0xffffffffu, acc.y, off);
        acc.z += __shfl_xor_sync(0xffffffffu, acc.z, off);
        acc.w += __shfl_xor_sync(0xffffffffu, acc.w, off);
    }

    if (lane < 8) {
        float4 b = bias4[lane];
        float4 r;
        r.x = acc.x + b.x; r.y = acc.y + b.y;
        r.z = acc.z + b.z; r.w = acc.w + b.w;
        out4[(size_t)n * 8 + lane] = r;
    }
}

// ---------------- BN stats over y ----------------
__global__ void bn_stats_k(const float* __restrict__ y,
                           float* __restrict__ bnsum, float* __restrict__ bnsq)
{
    __shared__ float s1[1024];
    __shared__ float s2[1024];
    int tid = threadIdx.x;
    int c = tid & 31;
    int n = blockIdx.x * 32 + (tid >> 5);
    float val = (n < NN) ? y[(size_t)n * 32 + c] : 0.f;
    s1[tid] = val;
    s2[tid] = val * val;
    __syncthreads();
    for (int st = 512; st >= 32; st >>= 1) {
        if (tid < st) { s1[tid] += s1[tid + st]; s2[tid] += s2[tid + st]; }
        __syncthreads();
    }
    if (tid < 32) {
        atomicAdd(&bnsum[tid * 32], s1[tid]);
        atomicAdd(&bnsq[tid * 32], s2[tid]);
    }
}

__global__ void bn_params_k(const float* __restrict__ bnsum, const float* __restrict__ bnsq,
                            const float* __restrict__ g, const float* __restrict__ be,
                            float* __restrict__ scale, float* __restrict__ shift)
{
    int c = threadIdx.x;
    if (c >= 32) return;
    float mu = bnsum[c * 32] * (1.f / NN);
    float var = bnsq[c * 32] * (1.f / NN) - mu * mu;
    float sc = g[c] * rsqrtf(var + BN_EPS);
    scale[c] = sc;
    shift[c] = be[c] - mu * sc;
}

// ---------------- host ----------------
extern "C" void kernel_launch(void* const* d_in, const int* in_sizes, int n_in,
                              void* d_out, int out_size)
{
    const float* x   = (const float*)d_in[0];
    const int*   ei  = (const int*)  d_in[1];
    const float* ea  = (const float*)d_in[2];
    const float* W[3]   = {(const float*)d_in[3],  (const float*)d_in[9],  (const float*)d_in[15]};
    const float* aS[3]  = {(const float*)d_in[4],  (const float*)d_in[10], (const float*)d_in[16]};
    const float* aD[3]  = {(const float*)d_in[5],  (const float*)d_in[11], (const float*)d_in[17]};
    const float* bia[3] = {(const float*)d_in[6],  (const float*)d_in[12], (const float*)d_in[18]};
    const float* gam[2] = {(const float*)d_in[7],  (const float*)d_in[13]};
    const float* bet[2] = {(const float*)d_in[8],  (const float*)d_in[14]};
    const int* src = ei;
    const int* dst = ei + NE;

    void *ph, *py, *pals, *pald, *pdeg, *prow, *pcur, *pcsr, *pbn, *psc, *psh;
    cudaGetSymbolAddress(&ph, g_h);
    cudaGetSymbolAddress(&py, g_y);
    cudaGetSymbolAddress(&pals, g_alS);
    cudaGetSymbolAddress(&pald, g_alD);
    cudaGetSymbolAddress(&pdeg, g_deg);
    cudaGetSymbolAddress(&prow, g_rowptr);
    cudaGetSymbolAddress(&pcur, g_cursor);
    cudaGetSymbolAddress(&pcsr, g_csr_src);
    cudaGetSymbolAddress(&pbn, g_bn);
    cudaGetSymbolAddress(&psc, g_scale);
    cudaGetSymbolAddress(&psh, g_shift);

    const int GEMM_BLOCKS = (NN + 127) / 128;     // 782
    const int EB = (NE + 255) / 256;              // 6250
    const int GB = (NN * 32 + 255) / 256;         // 12500
    const int BB = (NN + 31) / 32;                // 3125

    // ---- CSR build (once; reused by all 3 layers) ----
    cudaMemsetAsync(pdeg, 0, NN * sizeof(int));
    hist_k<<<EB, 256>>>(dst, (int*)pdeg);
    scan_k<<<1, 1024>>>((const int*)pdeg, (int*)prow, (int*)pcur);
    scatter_build_k<<<EB, 256>>>(src, dst, (int*)pcur, (int*)pcsr);

    for (int L = 0; L < 3; ++L) {
        if (L == 0) {
            gemm_al<128><<<GEMM_BLOCKS, 256>>>(
                x, W[0], aS[0], aD[0], nullptr, nullptr,
                (__half*)ph, (float*)pals, (float*)pald, 0);
        } else {
            gemm_al<32><<<GEMM_BLOCKS, 256>>>(
                (const float*)py, W[L], aS[L], aD[L],
                (const float*)psc, (const float*)psh,
                (__half*)ph, (float*)pals, (float*)pald, 1);
        }

        float* dest = (L < 2) ? (float*)py : (float*)d_out;
        gather_k<<<GB, 256>>>((const int*)prow, (const int*)pcsr,
                              (const float4*)pals, (const float4*)pald,
                              (const __half*)ph, (const float4*)bia[L],
                              (float4*)dest);

        if (L < 2) {
            cudaMemsetAsync(pbn, 0, 2 * 32 * 32 * sizeof(float));
            bn_stats_k<<<BB, 1024>>>((const float*)py, (float*)pbn, (float*)pbn + 1024);
            bn_params_k<<<1, 32>>>((const float*)pbn, (const float*)pbn + 1024,
                                   gam[L], bet[L], (float*)psc, (float*)psh);
        }
    }

    cudaMemcpyAsync((float*)d_out + (size_t)NN * 32, ea,
                    (size_t)NE * 8 * sizeof(float), cudaMemcpyDeviceToDevice);
}

// round 17
// speedup vs baseline: 1.1561x; 1.0477x over previous
#include <cuda_runtime.h>
#include <cuda_fp16.h>
#include <cstdint>

#define NN 100000
#define NE 1600000
#define NEG_SLOPE 0.2f
#define BN_EPS 1e-5f

// ---------------- scratch (static __device__, no allocation) ----------------
__device__ __align__(16) __half g_h[(size_t)NN * 128];  // GEMM output [N,4,32] fp16
__device__ __align__(16) float g_y[(size_t)NN * 32];    // per-layer node features
__device__ __align__(16) float g_alS[(size_t)NN * 4];
__device__ __align__(16) float g_alD[(size_t)NN * 4];
__device__ int g_deg[NN];
__device__ int g_rowptr[NN + 1];
__device__ int g_cursor[NN];
__device__ int g_csr_src[NE];
__device__ float g_bn[2 * 32 * 32];                     // strided sums / sumsq
__device__ float g_scale[32];
__device__ float g_shift[32];

__device__ __forceinline__ float leaky(float e) {
    return e >= 0.f ? e : NEG_SLOPE * e;
}

__device__ __forceinline__ void cp_async16(void* smem, const void* g) {
    unsigned s = (unsigned)__cvta_generic_to_shared(smem);
    asm volatile("cp.async.ca.shared.global [%0], [%1], 16;" :: "r"(s), "l"(g));
}

// ---------------- CSR build ----------------
__global__ void hist_k(const int* __restrict__ dst, int* __restrict__ deg) {
    int i = blockIdx.x * blockDim.x + threadIdx.x;
    if (i < NE) atomicAdd(&deg[dst[i]], 1);
}

__global__ void scan_k(const int* __restrict__ deg, int* __restrict__ rowptr,
                       int* __restrict__ cursor) {
    __shared__ int sc[1024];
    const int tid = threadIdx.x;
    const int CH = (NN + 1023) / 1024;  // 98
    const int base = tid * CH;
    int s = 0;
    for (int i = 0; i < CH; ++i) {
        int idx = base + i;
        if (idx < NN) s += deg[idx];
    }
    sc[tid] = s;
    __syncthreads();
    for (int off = 1; off < 1024; off <<= 1) {
        int v = (tid >= off) ? sc[tid - off] : 0;
        __syncthreads();
        sc[tid] += v;
        __syncthreads();
    }
    int run = sc[tid] - s;
    for (int i = 0; i < CH; ++i) {
        int idx = base + i;
        if (idx < NN) {
            rowptr[idx] = run;
            cursor[idx] = run;
            run += deg[idx];
        }
    }
    if (tid == 1023) rowptr[NN] = sc[1023];
}

__global__ void scatter_build_k(const int* __restrict__ src, const int* __restrict__ dst,
                                int* __restrict__ cursor, int* __restrict__ csr_src) {
    int i = blockIdx.x * blockDim.x + threadIdx.x;
    if (i >= NE) return;
    int p = atomicAdd(&cursor[dst[i]], 1);
    csr_src[p] = src[i];
}

// ---------------- GEMM + attention logits (fused prev-layer BN+ReLU) ----------------
// Register-blocked 128x128 tile, 256 threads, 8x8 micro-tile. Double-buffered
// k-pipeline: A prefetched via registers, B via cp.async. F=32 runs single-tile.
template<int F>
__global__ void gemm_al(const float* __restrict__ x,     // [N,F]
                        const float* __restrict__ W,     // [F,128] (k-major)
                        const float* __restrict__ aS,    // [128]
                        const float* __restrict__ aD,    // [128]
                        const float* __restrict__ scale, // [F] or null
                        const float* __restrict__ shift, // [F] or null
                        __half* __restrict__ h,          // [N,128] fp16
                        float* __restrict__ alS,         // [N,4]
                        float* __restrict__ alD,         // [N,4]
                        int useBN)
{
    extern __shared__ float sm[];
    float (*As)[32][132] = (float(*)[32][132])sm;                  // As[2]
    float (*Bs)[32][132] = (float(*)[32][132])(sm + 2 * 32 * 132); // Bs[2]
    const int tid = threadIdx.x;
    const int tx = tid & 15;
    const int ty = tid >> 4;
    const int n0 = blockIdx.x * 128;
    const int col0 = tx * 8;

    const int ar = tid >> 1;          // A-load row 0..127
    const int ah = (tid & 1) * 16;    // A-load k-half offset
    const int bk = tid >> 3;          // B-load k 0..31
    const int bs = (tid & 7) * 16;    // B-load col segment

    const int an = n0 + ar;
    const bool aok = (an < NN);
    const float* xrow = x + (size_t)an * F + ah;

    float4 areg[4];
    auto loadA = [&](int k0) {
#pragma unroll
        for (int q = 0; q < 4; ++q) {
            float4 v = make_float4(0.f, 0.f, 0.f, 0.f);
            if (aok) {
                v = *(const float4*)(xrow + k0 + q * 4);
                if (useBN) {
                    int k = k0 + ah + q * 4;
                    v.x = fmaxf(fmaf(v.x, scale[k],     shift[k]),     0.f);
                    v.y = fmaxf(fmaf(v.y, scale[k + 1], shift[k + 1]), 0.f);
                    v.z = fmaxf(fmaf(v.z, scale[k + 2], shift[k + 2]), 0.f);
                    v.w = fmaxf(fmaf(v.w, scale[k + 3], shift[k + 3]), 0.f);
                }
            }
            areg[q] = v;
        }
    };
    auto storeA = [&](int b) {
#pragma unroll
        for (int q = 0; q < 4; ++q) {
            As[b][ah + q * 4 + 0][ar] = areg[q].x;
            As[b][ah + q * 4 + 1][ar] = areg[q].y;
            As[b][ah + q * 4 + 2][ar] = areg[q].z;
            As[b][ah + q * 4 + 3][ar] = areg[q].w;
        }
    };
    auto loadB = [&](int k0, int b) {
        const float* wp = W + (size_t)(k0 + bk) * 128 + bs;
#pragma unroll
        for (int q = 0; q < 4; ++q)
            cp_async16(&Bs[b][bk][bs + q * 4], wp + q * 4);
        asm volatile("cp.async.commit_group;" ::: "memory");
    };

    float acc[8][8];
#pragma unroll
    for (int i = 0; i < 8; ++i)
#pragma unroll
        for (int j = 0; j < 8; ++j) acc[i][j] = 0.f;

    // prologue: tile 0
    loadA(0);
    loadB(0, 0);
    storeA(0);
    asm volatile("cp.async.wait_group 0;" ::: "memory");
    __syncthreads();

    int buf = 0;
    for (int k0 = 0; k0 < F; k0 += 32) {
        const bool more = (k0 + 32 < F);
        if (more) {
            loadA(k0 + 32);        // LDGs in flight during compute
            loadB(k0 + 32, buf ^ 1);
        }

#pragma unroll 4
        for (int k = 0; k < 32; ++k) {
            float4 a0 = *(const float4*)&As[buf][k][ty * 8];
            float4 a1 = *(const float4*)&As[buf][k][ty * 8 + 4];
            float4 b0 = *(const float4*)&Bs[buf][k][col0];
            float4 b1 = *(const float4*)&Bs[buf][k][col0 + 4];
            float a[8] = {a0.x, a0.y, a0.z, a0.w, a1.x, a1.y, a1.z, a1.w};
            float b[8] = {b0.x, b0.y, b0.z, b0.w, b1.x, b1.y, b1.z, b1.w};
#pragma unroll
            for (int i = 0; i < 8; ++i)
#pragma unroll
                for (int j = 0; j < 8; ++j)
                    acc[i][j] = fmaf(a[i], b[j], acc[i][j]);
        }

        if (more) {
            storeA(buf ^ 1);
            asm volatile("cp.async.wait_group 0;" ::: "memory");
        }
        __syncthreads();
        buf ^= 1;
    }

    // ---- epilogue: fp16 h stores + fused attention logits ----
    float4 s0 = *(const float4*)(aS + col0);
    float4 s1 = *(const float4*)(aS + col0 + 4);
    float4 d0 = *(const float4*)(aD + col0);
    float4 d1 = *(const float4*)(aD + col0 + 4);
    float aSv[8] = {s0.x, s0.y, s0.z, s0.w, s1.x, s1.y, s1.z, s1.w};
    float aDv[8] = {d0.x, d0.y, d0.z, d0.w, d1.x, d1.y, d1.z, d1.w};

#pragma unroll
    for (int i = 0; i < 8; ++i) {
        int n = n0 + ty * 8 + i;
        bool ok = (n < NN);
        if (ok) {
            __half hv[8];
#pragma unroll
            for (int j = 0; j < 8; ++j) hv[j] = __float2half(acc[i][j]);
            *(uint4*)&h[(size_t)n * 128 + col0] = *(const uint4*)hv;
        }
        float vs = 0.f, vd = 0.f;
#pragma unroll
        for (int j = 0; j < 8; ++j) {
            vs = fmaf(acc[i][j], aSv[j], vs);
            vd = fmaf(acc[i][j], aDv[j], vd);
        }
        vs += __shfl_xor_sync(0xffffffffu, vs, 1);
        vd += __shfl_xor_sync(0xffffffffu, vd, 1);
        vs += __shfl_xor_sync(0xffffffffu, vs, 2);
        vd += __shfl_xor_sync(0xffffffffu, vd, 2);
        if ((tx & 3) == 0 && ok) {
            alS[n * 4 + (tx >> 2)] = vs;
            alD[n * 4 + (tx >> 2)] = vd;
        }
    }
}

// ---------------- fused attention + aggregate + head-mean + bias + BN stats ----------------
__global__ void gather_k(const int* __restrict__ rowptr,
                         const int* __restrict__ csr_src,
                         const float4* __restrict__ alS4,  // [N] (4 heads)
                         const float4* __restrict__ alD4,  // [N]
                         const __half* __restrict__ h,     // [N,128] fp16
                         const float4* __restrict__ bias4, // [8]
                         float4* __restrict__ out4,        // [N,8] float4
                         float* __restrict__ bnsum,        // strided [32*32]
                         float* __restrict__ bnsq,
                         int doBN)
{
    __shared__ float4 s_ee[8][32];
    __shared__ int    s_sid[8][32];
    __shared__ float  sSum[32], sSq[32];
    const int tid = threadIdx.x;
    if (doBN && tid < 32) { sSum[tid] = 0.f; sSq[tid] = 0.f; }
    __syncthreads();

    int gid = blockIdx.x * blockDim.x + tid;
    int n = gid >> 5;
    const int warp = tid >> 5;
    const int lane = gid & 31;
    const int head = lane >> 3;

    float4 acc = make_float4(0.f, 0.f, 0.f, 0.f);
    float4 r   = make_float4(0.f, 0.f, 0.f, 0.f);

    if (n < NN) {
        const int beg = rowptr[n];
        const int end = rowptr[n + 1];
        const float4 ad4 = alD4[n];

        float4 den4 = make_float4(0.f, 0.f, 0.f, 0.f);

        for (int base = beg; base < end; base += 32) {
            const int cnt = min(32, end - base);
            if (lane < cnt) {
                int s = csr_src[base + lane];
                float4 a = alS4[s];
                float4 ee;
                ee.x = __expf(leaky(a.x + ad4.x));
                ee.y = __expf(leaky(a.y + ad4.y));
                ee.z = __expf(leaky(a.z + ad4.z));
                ee.w = __expf(leaky(a.w + ad4.w));
                den4.x += ee.x; den4.y += ee.y; den4.z += ee.z; den4.w += ee.w;
                s_sid[warp][lane] = s;
                s_ee[warp][lane] = ee;
            }
            __syncwarp();
            int j = 0;
            for (; j + 4 <= cnt; j += 4) {
                int s0 = s_sid[warp][j];
                int s1 = s_sid[warp][j + 1];
                int s2 = s_sid[warp][j + 2];
                int s3 = s_sid[warp][j + 3];
                float w0 = reinterpret_cast<const float*>(&s_ee[warp][j])[head];
                float w1 = reinterpret_cast<const float*>(&s_ee[warp][j + 1])[head];
                float w2 = reinterpret_cast<const float*>(&s_ee[warp][j + 2])[head];
                float w3 = reinterpret_cast<const float*>(&s_ee[warp][j + 3])[head];
                uint2 r0 = *(const uint2*)(h + (size_t)s0 * 128 + lane * 4);
                uint2 r1 = *(const uint2*)(h + (size_t)s1 * 128 + lane * 4);
                uint2 r2 = *(const uint2*)(h + (size_t)s2 * 128 + lane * 4);
                uint2 r3 = *(const uint2*)(h + (size_t)s3 * 128 + lane * 4);
                float2 f0a = __half22float2(*reinterpret_cast<__half2*>(&r0.x));
                float2 f0b = __half22float2(*reinterpret_cast<__half2*>(&r0.y));
                float2 f1a = __half22float2(*reinterpret_cast<__half2*>(&r1.x));
                float2 f1b = __half22float2(*reinterpret_cast<__half2*>(&r1.y));
                float2 f2a = __half22float2(*reinterpret_cast<__half2*>(&r2.x));
                float2 f2b = __half22float2(*reinterpret_cast<__half2*>(&r2.y));
                float2 f3a = __half22float2(*reinterpret_cast<__half2*>(&r3.x));
                float2 f3b = __half22float2(*reinterpret_cast<__half2*>(&r3.y));
                acc.x = fmaf(w0, f0a.x, acc.x); acc.y = fmaf(w0, f0a.y, acc.y);
                acc.z = fmaf(w0, f0b.x, acc.z); acc.w = fmaf(w0, f0b.y, acc.w);
                acc.x = fmaf(w1, f1a.x, acc.x); acc.y = fmaf(w1, f1a.y, acc.y);
                acc.z = fmaf(w1, f1b.x, acc.z); acc.w = fmaf(w1, f1b.y, acc.w);
                acc.x = fmaf(w2, f2a.x, acc.x); acc.y = fmaf(w2, f2a.y, acc.y);
                acc.z = fmaf(w2, f2b.x, acc.z); acc.w = fmaf(w2, f2b.y, acc.w);
                acc.x = fmaf(w3, f3a.x, acc.x); acc.y = fmaf(w3, f3a.y, acc.y);
                acc.z = fmaf(w3, f3b.x, acc.z); acc.w = fmaf(w3, f3b.y, acc.w);
            }
            for (; j < cnt; ++j) {
                int s = s_sid[warp][j];
                float w = reinterpret_cast<const float*>(&s_ee[warp][j])[head];
                uint2 rr = *(const uint2*)(h + (size_t)s * 128 + lane * 4);
                float2 fa = __half22float2(*reinterpret_cast<__half2*>(&rr.x));
                float2 fb = __half22float2(*reinterpret_cast<__half2*>(&rr.y));
                acc.x = fmaf(w, fa.x, acc.x);
                acc.y = fmaf(w, fa.y, acc.y);
                acc.z = fmaf(w, fb.x, acc.z);
                acc.w = fmaf(w, fb.y, acc.w);
            }
            __syncwarp();
        }

#pragma unroll
        for (int off = 16; off > 0; off >>= 1) {
            den4.x += __shfl_xor_sync(0xffffffffu, den4.x, off);
            den4.y += __shfl_xor_sync(0xffffffffu, den4.y, off);
            den4.z += __shfl_xor_sync(0xffffffffu, den4.z, off);
            den4.w += __shfl_xor_sync(0xffffffffu, den4.w, off);
        }
        const float den = (head == 0) ? den4.x : (head == 1) ? den4.y
                        : (head == 2) ? den4.z : den4.w;
        const float wsc = (den > 0.f) ? 0.25f / den : 0.f;
        acc.x *= wsc; acc.y *= wsc; acc.z *= wsc; acc.w *= wsc;

#pragma unroll
        for (int off = 8; off <= 16; off <<= 1) {
            acc.x += __shfl_xor_sync(0xffffffffu, acc.x, off);
            acc.y += __shfl_xor_sync(0xffffffffu, acc.y, off);
            acc.z += __shfl_xor_sync(0xffffffffu, acc.z, off);
            acc.w += __shfl_xor_sync(0xffffffffu, acc.w, off);
        }

        if (lane < 8) {
            float4 b = bias4[lane];
            r.x = acc.x + b.x; r.y = acc.y + b.y;
            r.z = acc.z + b.z; r.w = acc.w + b.w;
            out4[(size_t)n * 8 + lane] = r;
        }
    }

    // ---- fused BN stats (block-reduce then one strided global atomic set) ----
    if (doBN) {
        if (n < NN && lane < 8) {
            int c = lane * 4;
            atomicAdd(&sSum[c + 0], r.x); atomicAdd(&sSq[c + 0], r.x * r.x);
            atomicAdd(&sSum[c + 1], r.y); atomicAdd(&sSq[c + 1], r.y * r.y);
            atomicAdd(&sSum[c + 2], r.z); atomicAdd(&sSq[c + 2], r.z * r.z);
            atomicAdd(&sSum[c + 3], r.w); atomicAdd(&sSq[c + 3], r.w * r.w);
        }
        __syncthreads();
        if (tid < 32) {
            atomicAdd(&bnsum[tid * 32], sSum[tid]);
            atomicAdd(&bnsq[tid * 32],  sSq[tid]);
        }
    }
}

__global__ void bn_params_k(const float* __restrict__ bnsum, const float* __restrict__ bnsq,
                            const float* __restrict__ g, const float* __restrict__ be,
                            float* __restrict__ scale, float* __restrict__ shift)
{
    int c = threadIdx.x;
    if (c >= 32) return;
    float mu = bnsum[c * 32] * (1.f / NN);
    float var = bnsq[c * 32] * (1.f / NN) - mu * mu;
    float sc = g[c] * rsqrtf(var + BN_EPS);
    scale[c] = sc;
    shift[c] = be[c] - mu * sc;
}

// ---------------- host ----------------
extern "C" void kernel_launch(void* const* d_in, const int* in_sizes, int n_in,
                              void* d_out, int out_size)
{
    const float* x   = (const float*)d_in[0];
    const int*   ei  = (const int*)  d_in[1];
    const float* ea  = (const float*)d_in[2];
    const float* W[3]   = {(const float*)d_in[3],  (const float*)d_in[9],  (const float*)d_in[15]};
    const float* aS[3]  = {(const float*)d_in[4],  (const float*)d_in[10], (const float*)d_in[16]};
    const float* aD[3]  = {(const float*)d_in[5],  (const float*)d_in[11], (const float*)d_in[17]};
    const float* bia[3] = {(const float*)d_in[6],  (const float*)d_in[12], (const float*)d_in[18]};
    const float* gam[2] = {(const float*)d_in[7],  (const float*)d_in[13]};
    const float* bet[2] = {(const float*)d_in[8],  (const float*)d_in[14]};
    const int* src = ei;
    const int* dst = ei + NE;

    void *ph, *py, *pals, *pald, *pdeg, *prow, *pcur, *pcsr, *pbn, *psc, *psh;
    cudaGetSymbolAddress(&ph, g_h);
    cudaGetSymbolAddress(&py, g_y);
    cudaGetSymbolAddress(&pals, g_alS);
    cudaGetSymbolAddress(&pald, g_alD);
    cudaGetSymbolAddress(&pdeg, g_deg);
    cudaGetSymbolAddress(&prow, g_rowptr);
    cudaGetSymbolAddress(&pcur, g_cursor);
    cudaGetSymbolAddress(&pcsr, g_csr_src);
    cudaGetSymbolAddress(&pbn, g_bn);
    cudaGetSymbolAddress(&psc, g_scale);
    cudaGetSymbolAddress(&psh, g_shift);

    const int SMEM = 4 * 32 * 132 * 4;            // 67584 B (2xAs + 2xBs)
    cudaFuncSetAttribute(gemm_al<128>, cudaFuncAttributeMaxDynamicSharedMemorySize, SMEM);
    cudaFuncSetAttribute(gemm_al<32>,  cudaFuncAttributeMaxDynamicSharedMemorySize, SMEM);

    const int GEMM_BLOCKS = (NN + 127) / 128;     // 782
    const int EB = (NE + 255) / 256;              // 6250
    const int GB = (NN * 32 + 255) / 256;         // 12500

    // ---- CSR build (once; reused by all 3 layers) ----
    cudaMemsetAsync(pdeg, 0, NN * sizeof(int));
    hist_k<<<EB, 256>>>(dst, (int*)pdeg);
    scan_k<<<1, 1024>>>((const int*)pdeg, (int*)prow, (int*)pcur);
    scatter_build_k<<<EB, 256>>>(src, dst, (int*)pcur, (int*)pcsr);

    for (int L = 0; L < 3; ++L) {
        if (L == 0) {
            gemm_al<128><<<GEMM_BLOCKS, 256, SMEM>>>(
                x, W[0], aS[0], aD[0], nullptr, nullptr,
                (__half*)ph, (float*)pals, (float*)pald, 0);
        } else {
            gemm_al<32><<<GEMM_BLOCKS, 256, SMEM>>>(
                (const float*)py, W[L], aS[L], aD[L],
                (const float*)psc, (const float*)psh,
                (__half*)ph, (float*)pals, (float*)pald, 1);
        }

        if (L < 2) cudaMemsetAsync(pbn, 0, 2 * 32 * 32 * sizeof(float));

        float* dest = (L < 2) ? (float*)py : (float*)d_out;
        gather_k<<<GB, 256>>>((const int*)prow, (const int*)pcsr,
                              (const float4*)pals, (const float4*)pald,
                              (const __half*)ph, (const float4*)bia[L],
                              (float4*)dest,
                              (float*)pbn, (float*)pbn + 1024, (L < 2) ? 1 : 0);

        if (L < 2) {
            bn_params_k<<<1, 32>>>((const float*)pbn, (const float*)pbn + 1024,
                                   gam[L], bet[L], (float*)psc, (float*)psh);
        }
    }

    cudaMemcpyAsync((float*)d_out + (size_t)NN * 32, ea,
                    (size_t)NE * 8 * sizeof(float), cudaMemcpyDeviceToDevice);
}